// round 7
// baseline (speedup 1.0000x reference)
#include <cuda_runtime.h>
#include <cstdint>

// DetectionFocalLoss — warp-transposed coalesced single-kernel version.
//   d_in[0] classifications float32 (B,N,C)
//   d_in[1] regressions     float32 (B,N,4)
//   d_in[2] anchors         float32 (1,N,4)  [cx,cy,w,h]
//   d_in[3] annotations     float32 (B,M,5)  [x1,y1,x2,y2,cls]
// Output: float32[2]

#define TPB 256
#define NBMAX 4096
#define BMAX 16
#define MMAX 128

__device__ float g_pcl[BMAX * NBMAX];
__device__ float g_psl[BMAX * NBMAX];
__device__ float g_pct[BMAX * NBMAX];
__device__ unsigned g_done = 0;

__device__ __forceinline__ float clip_cls(float x) {
    return fminf(fmaxf(x, 1e-4f), 1.0f - 1e-4f);
}

// focal term for label==0: (1-ALPHA) * cls^2 * (-log(1-cls))
__device__ __forceinline__ float f_neg(float x) {
    float xc = clip_cls(x);
    return 0.75f * xc * xc * (-__logf(1.0f - xc));
}

// C4_CT: compile-time C/4 (0 => use runtime c4 param)
template <int C4_CT>
__global__ __launch_bounds__(TPB)
void fused_kernel(const float* __restrict__ cls_,
                  const float* __restrict__ reg_,
                  const float* __restrict__ anc,
                  const float* __restrict__ ann,
                  float* __restrict__ out,
                  int N, int c4_rt, int M, int NB, int B)
{
    const int C4 = (C4_CT > 0) ? C4_CT : c4_rt;
    const int C  = C4 * 4;

    __shared__ float s_ann[MMAX * 5];
    __shared__ float s_area[MMAX];
    __shared__ float w_cl[8], w_sl[8], w_ct[8];
    __shared__ unsigned s_rank;
    __shared__ float f_cls[BMAX], f_es[BMAX], f_ec[BMAX];

    const int b    = blockIdx.y;
    const int tid  = threadIdx.x;
    const int ww   = tid >> 5;
    const int lane = tid & 31;
    const int nb   = (blockIdx.x * 8 + ww) * 32;   // warp's first anchor
    const int n    = nb + lane;                     // this lane's anchor

    // stage annotations for this batch
    for (int i = tid; i < M * 5; i += TPB)
        s_ann[i] = ann[(size_t)b * M * 5 + i];
    __syncthreads();
    if (tid < M) {
        float x1 = s_ann[tid * 5 + 0], y1 = s_ann[tid * 5 + 1];
        float x2 = s_ann[tid * 5 + 2], y2 = s_ann[tid * 5 + 3];
        s_area[tid] = (x2 - x1) * (y2 - y1);
    }
    __syncthreads();

    // ---- per-lane anchor assignment (IoU max/argmax) ----
    float4 a = make_float4(0.f, 0.f, 1.f, 1.f);
    bool pos = false;
    int  bi  = 0;
    if (n < N) {
        a = reinterpret_cast<const float4*>(anc)[n];
        float t0 = a.x - a.z * 0.5f;
        float t1 = a.y - a.w * 0.5f;
        float t2 = a.x + a.z * 0.5f;
        float t3 = a.y + a.w * 0.5f;
        float area_a = (t2 - t0) * (t3 - t1);

        float best = -1.0f;
        #pragma unroll 4
        for (int m = 0; m < M; m++) {
            float b0 = s_ann[m * 5 + 0], b1 = s_ann[m * 5 + 1];
            float b2 = s_ann[m * 5 + 2], b3 = s_ann[m * 5 + 3];
            float lx = fmaxf(t0, b0), ly = fmaxf(t1, b1);
            float rx = fminf(t2, b2), ry = fminf(t3, b3);
            float wi = fmaxf(rx - lx, 0.0f);
            float hi = fmaxf(ry - ly, 0.0f);
            float inter = wi * hi;
            float uni = area_a + s_area[m] - inter;
            float iou = inter / fmaxf(uni, 1e-8f);
            if (iou > best) { best = iou; bi = m; }   // first-max (argmax)
        }
        pos = (best >= 0.5f);
        bool neg = (best <= 0.4f);
        (void)neg;
        // valid = contributes cls terms (pos or neg); ignore-band excluded
        // (flag packed into ballot below)
        if (!(pos || (best <= 0.4f))) bi = bi; // no-op; clarity
    }
    bool neg_ok = false;
    if (n < N) {
        // recompute cheap flag for ballot clarity: pos||neg
        // (best not kept; derive from pos and band via second pass avoided —
        //  carry it through a bool computed above instead)
    }
    // carry valid flag properly: recompute inside the n<N block
    // -> done via 'valid_lane' below
    bool valid_lane = false;
    if (n < N) {
        // redo the tiny comparison using stored pos + a second max pass is
        // wasteful; instead recompute best cheaply is not needed: we kept pos,
        // and need neg. Compute neg from scratch would repeat the loop, so we
        // instead folded it here:
        valid_lane = true;  // placeholder, fixed right below
    }
    // NOTE: to avoid a second IoU pass we fold neg detection into the first
    // pass: redo with explicit flags (compiler keeps one loop).
    // --- (restructured cleanly below) ---

    // The above bookkeeping is eliminated by computing flags in one pass:
    // re-run assignment storing both flags (the optimizer merges).
    bool posf = false, validf = false;
    {
        if (n < N) {
            float t0 = a.x - a.z * 0.5f;
            float t1 = a.y - a.w * 0.5f;
            float t2 = a.x + a.z * 0.5f;
            float t3 = a.y + a.w * 0.5f;
            float area_a = (t2 - t0) * (t3 - t1);
            float best = -1.0f;
            int   bj = 0;
            #pragma unroll 4
            for (int m = 0; m < M; m++) {
                float b0 = s_ann[m * 5 + 0], b1 = s_ann[m * 5 + 1];
                float b2 = s_ann[m * 5 + 2], b3 = s_ann[m * 5 + 3];
                float lx = fmaxf(t0, b0), ly = fmaxf(t1, b1);
                float rx = fminf(t2, b2), ry = fminf(t3, b3);
                float wi = fmaxf(rx - lx, 0.0f);
                float hi = fmaxf(ry - ly, 0.0f);
                float inter = wi * hi;
                float uni = area_a + s_area[m] - inter;
                float iou = inter / fmaxf(uni, 1e-8f);
                if (iou > best) { best = iou; bj = m; }
            }
            posf   = (best >= 0.5f);
            validf = posf || (best <= 0.4f);
            bi = bj;
        }
    }
    pos = posf;
    (void)valid_lane; (void)neg_ok;

    const unsigned valid_mask = __ballot_sync(0xFFFFFFFFu, validf);

    // ---- warp-transposed coalesced class-loss sum ----
    float cl = 0.0f;
    if (nb < N) {
        const float4* p4 =
            reinterpret_cast<const float4*>(cls_ + ((size_t)b * N + nb) * C);
        if (nb + 32 <= N) {
            #pragma unroll
            for (int j = 0; j < ((C4_CT > 0) ? C4_CT : 1); j++) {
                // when C4_CT==0 this unroll pragma is inert; loop below
                if (C4_CT > 0) {
                    int k = j * 32 + lane;
                    int r = k / C4;                  // row within warp tile
                    float4 v = p4[k];
                    float t = f_neg(v.x) + f_neg(v.y) + f_neg(v.z) + f_neg(v.w);
                    cl += ((valid_mask >> r) & 1u) ? t : 0.0f;
                }
            }
            if (C4_CT == 0) {
                for (int j = 0; j < C4; j++) {
                    int k = j * 32 + lane;
                    int r = k / C4;
                    float4 v = p4[k];
                    float t = f_neg(v.x) + f_neg(v.y) + f_neg(v.z) + f_neg(v.w);
                    cl += ((valid_mask >> r) & 1u) ? t : 0.0f;
                }
            }
        } else {
            // tail warp: guard rows beyond N
            for (int j = 0; j < C4; j++) {
                int k = j * 32 + lane;
                int r = k / C4;
                if ((nb + r) < N && ((valid_mask >> r) & 1u)) {
                    float4 v = p4[k];
                    cl += f_neg(v.x) + f_neg(v.y) + f_neg(v.z) + f_neg(v.w);
                }
            }
        }
    }

    // ---- per-lane positive-anchor correction + smooth-L1 ----
    float sl = 0.0f;
    float ctf = 0.0f;
    if (pos) {
        ctf = 1.0f;
        const float* cp = cls_ + ((size_t)b * N + n) * C;
        int cid = (int)s_ann[bi * 5 + 4];
        float x = clip_cls(cp[cid]);
        cl -= 0.75f * x * x * (-__logf(1.0f - x));
        float om = 1.0f - x;
        cl += 0.25f * om * om * (-__logf(x));

        float4 r = reinterpret_cast<const float4*>(reg_)[(size_t)b * N + n];
        float g0 = s_ann[bi * 5 + 0], g1 = s_ann[bi * 5 + 1];
        float g2 = s_ann[bi * 5 + 2], g3 = s_ann[bi * 5 + 3];
        float dw  = g2 - g0;
        float dh  = g3 - g1;
        float dxc = g0 + g2 * 0.5f;    // replicate reference exactly
        float dyc = g1 + g3 * 0.5f;
        float dx  = (dxc - a.x) / a.z;
        float dy  = (dyc - a.y) / a.w;
        float dwl = __logf(dw / a.z);
        float dhl = __logf(dh / a.w);
        float d0 = fabsf(r.x / 0.1f - dx  / 0.1f);
        float d1 = fabsf(r.y / 0.1f - dy  / 0.1f);
        float d2 = fabsf(r.z / 0.2f - dwl / 0.2f);
        float d3 = fabsf(r.w / 0.2f - dhl / 0.2f);
        float s0 = (d0 < 1.0f) ? 0.5f * d0 * d0 : d0 - 0.5f;
        float s1 = (d1 < 1.0f) ? 0.5f * d1 * d1 : d1 - 0.5f;
        float s2 = (d2 < 1.0f) ? 0.5f * d2 * d2 : d2 - 0.5f;
        float s3 = (d3 < 1.0f) ? 0.5f * d3 * d3 : d3 - 0.5f;
        sl = s0 + s1 + s2 + s3;
    }

    // ---- deterministic warp xor-tree reduction ----
    #pragma unroll
    for (int o = 16; o > 0; o >>= 1) {
        cl  += __shfl_xor_sync(0xFFFFFFFFu, cl,  o);
        sl  += __shfl_xor_sync(0xFFFFFFFFu, sl,  o);
        ctf += __shfl_xor_sync(0xFFFFFFFFu, ctf, o);
    }
    if (lane == 0) { w_cl[ww] = cl; w_sl[ww] = sl; w_ct[ww] = ctf; }
    __syncthreads();

    if (tid == 0) {
        float acl = 0.f, asl = 0.f, act = 0.f;
        #pragma unroll
        for (int i = 0; i < 8; i++) { acl += w_cl[i]; asl += w_sl[i]; act += w_ct[i]; }
        int p = b * NB + blockIdx.x;
        g_pcl[p] = acl;
        g_psl[p] = asl;
        g_pct[p] = act;
        __threadfence();
        s_rank = atomicAdd(&g_done, 1u);
    }
    __syncthreads();

    // ---- last block finalizes (single-kernel, no second launch) ----
    if (s_rank == (unsigned)(NB * B) - 1u) {
        __threadfence();  // acquire all partials
        for (int bb = ww; bb < B; bb += 8) {
            float cl2 = 0.f, sl2 = 0.f, ct2 = 0.f;
            for (int i = lane; i < NB; i += 32) {
                cl2 += g_pcl[bb * NB + i];
                sl2 += g_psl[bb * NB + i];
                ct2 += g_pct[bb * NB + i];
            }
            #pragma unroll
            for (int o = 16; o > 0; o >>= 1) {
                cl2 += __shfl_xor_sync(0xFFFFFFFFu, cl2, o);
                sl2 += __shfl_xor_sync(0xFFFFFFFFu, sl2, o);
                ct2 += __shfl_xor_sync(0xFFFFFFFFu, ct2, o);
            }
            if (lane == 0) {
                float denom    = fmaxf(ct2, 1.0f);
                float cls_loss = cl2 / denom;
                float reg_mean = sl2 / (denom * 4.0f);
                bool  has_pos  = (ct2 > 0.0f);
                f_cls[bb] = cls_loss;
                f_es[bb]  = has_pos ? (reg_mean / denom + reg_mean) : 0.0f;
                f_ec[bb]  = has_pos ? 2.0f : 1.0f;
            }
        }
        __syncthreads();
        if (tid == 0) {
            float acl = 0.f, aes = 0.f, aec = 0.f;
            for (int i = 0; i < B; i++) { acl += f_cls[i]; aes += f_es[i]; aec += f_ec[i]; }
            out[0] = acl / (float)B;
            out[1] = aes / aec;
            g_done = 0;   // reset for graph replay determinism
        }
    }
}

extern "C" void kernel_launch(void* const* d_in, const int* in_sizes, int n_in,
                              void* d_out, int out_size)
{
    const float* cls_ = (const float*)d_in[0];
    const float* reg_ = (const float*)d_in[1];
    const float* anc  = (const float*)d_in[2];
    const float* ann  = (const float*)d_in[3];
    float* out = (float*)d_out;

    int N = in_sizes[2] / 4;
    int B = in_sizes[1] / (N * 4);
    int C = in_sizes[0] / (B * N);
    int M = in_sizes[3] / (B * 5);

    int NB = (N + TPB - 1) / TPB;   // each block: 8 warps x 32 anchors = 256

    dim3 grid(NB, B);
    if (C == 80) {
        fused_kernel<20><<<grid, TPB>>>(cls_, reg_, anc, ann, out, N, C / 4, M, NB, B);
    } else {
        fused_kernel<0><<<grid, TPB>>>(cls_, reg_, anc, ann, out, N, C / 4, M, NB, B);
    }
}